// round 14
// baseline (speedup 1.0000x reference)
#include <cuda_runtime.h>
#include <cuda_bf16.h>
#include <cuda_fp16.h>
#include <math.h>
#include <stdint.h>

#define Bq 2
#define Tq 2048
#define Hq 12
#define Eq 64
#define Mq 256
#define NB 32
#define BH 24
#define ROWSTRIDE (Hq*Eq)

#define TEMP 0.125f
#define DN 0.35355339059327379f
#define HALF_LOG_M 2.7725887222397811f
#define NEG_INF __int_as_float(0xff800000)
#define KS 0.00390625f                 // 2^-8 prime-side (k) scale
#define LOG_KS 5.5451774444795624753f  // -log(KS) = 8*ln2
#define SQ 8.0f                        // fixed q-side shift

// ---------------- device scratch ----------------
__device__ uint32_t g_pbf[16384];                // proj*DN bf16 planes
__device__ uint32_t g_qbf[BH*NB*4096];           // raw q bf16 planes [row][e]
__device__ uint32_t g_kbf[BH*NB*4096];           // raw k bf16 planes
__device__ __align__(16) uint32_t g_qpb[BH*NB*8192]; // q'=exp(qd-SQ) fp16 packed [i][m/2]
__device__ __align__(16) uint32_t g_kpb[BH*NB*8192]; // k'*KS fp16 packed [j][m/2]
__device__ float g_qls [BH*Tq];
__device__ float g_kps [BH*Mq];                  // KS-scaled totals
__device__ float g_kvtot [BH*Mq*Eq];             // KS-scaled kv totals [m][d] f32
__device__ float g_kvpart [BH*32*Mq*Eq];         // KS-scaled kv partials [m][d]
__device__ float g_kpspart[BH*32*Mq];
__device__ __align__(16) unsigned short g_kvcmp[BH*NB*Eq*Mq]; // kv complement fp16 [d][m] per q-block
__device__ float g_kpscmp[BH*NB*Mq];             // kps complement per q-block

// ---------------- helpers ----------------
__device__ __forceinline__ void mma_bf16(float c[4],
        uint32_t a0, uint32_t a1, uint32_t a2, uint32_t a3, uint32_t b0, uint32_t b1)
{
    asm volatile(
        "mma.sync.aligned.m16n8k16.row.col.f32.bf16.bf16.f32 "
        "{%0,%1,%2,%3}, {%4,%5,%6,%7}, {%8,%9}, {%0,%1,%2,%3};\n"
        : "+f"(c[0]), "+f"(c[1]), "+f"(c[2]), "+f"(c[3])
        : "r"(a0), "r"(a1), "r"(a2), "r"(a3), "r"(b0), "r"(b1));
}

__device__ __forceinline__ void mma_f16(float c[4],
        uint32_t a0, uint32_t a1, uint32_t a2, uint32_t a3, uint32_t b0, uint32_t b1)
{
    asm volatile(
        "mma.sync.aligned.m16n8k16.row.col.f32.f16.f16.f32 "
        "{%0,%1,%2,%3}, {%4,%5,%6,%7}, {%8,%9}, {%0,%1,%2,%3};\n"
        : "+f"(c[0]), "+f"(c[1]), "+f"(c[2]), "+f"(c[3])
        : "r"(a0), "r"(a1), "r"(a2), "r"(a3), "r"(b0), "r"(b1));
}

__device__ __forceinline__ void split2_bf16(float x, float y, uint32_t &hi, uint32_t &lo) {
    __nv_bfloat16 hx = __float2bfloat16(x);
    __nv_bfloat16 hy = __float2bfloat16(y);
    __nv_bfloat16 lx = __float2bfloat16(x - __bfloat162float(hx));
    __nv_bfloat16 ly = __float2bfloat16(y - __bfloat162float(hy));
    hi = ((uint32_t)__bfloat16_as_ushort(hy) << 16) | (uint32_t)__bfloat16_as_ushort(hx);
    lo = ((uint32_t)__bfloat16_as_ushort(ly) << 16) | (uint32_t)__bfloat16_as_ushort(lx);
}

__device__ __forceinline__ uint32_t pack_f16(float x, float y) {
    __half2 h = __floats2half2_rn(x, y);
    return *reinterpret_cast<uint32_t*>(&h);
}
__device__ __forceinline__ float f16lo(uint32_t u) {
    return __half2float(__ushort_as_half((unsigned short)(u & 0xffffu)));
}
__device__ __forceinline__ float f16hi(uint32_t u) {
    return __half2float(__ushort_as_half((unsigned short)(u >> 16)));
}
__device__ __forceinline__ float bf16lo_f(uint32_t u) {
    return __bfloat162float(__ushort_as_bfloat16((unsigned short)(u & 0xffffu)));
}
__device__ __forceinline__ float bf16hi_f(uint32_t u) {
    return __bfloat162float(__ushort_as_bfloat16((unsigned short)(u >> 16)));
}

// ---------------- kernel 0: proj planes precompute ----------------
__global__ void pinit_kernel(const float* __restrict__ proj) {
    int idx = blockIdx.x*256 + threadIdx.x;
    if (idx < 8192) {
        int c = idx >> 11, rem = idx & 2047;
        int mm = rem >> 5, eh = rem & 31;
        float2 v = *(const float2*)(proj + (size_t)(c*64 + mm)*64 + eh*2);
        uint32_t hi, lo;
        split2_bf16(v.x * DN, v.y * DN, hi, lo);
        g_pbf[c*4096 + mm*32 + eh]        = hi;
        g_pbf[c*4096 + 2048 + mm*32 + eh] = lo;
    }
}

// ---------------- kernel 1: sides (unchanged from R13) ----------------
#define SD_UTQ  4608
#define SD_UP   9216
#define SD_DIAG 13824
#define SD_PART 13952
#define SD_KP16 14976
#define SD_VT   24192
#define SM_SIDES_FLOATS 26496

__global__ __launch_bounds__(256,2) void sides_kernel(const float* __restrict__ key,
                                                      const float* __restrict__ query,
                                                      const float* __restrict__ value) {
    extern __shared__ float sm[];
    uint32_t* uTk = (uint32_t*)sm;
    uint32_t* uTq = (uint32_t*)(sm + SD_UTQ);
    uint32_t* uP  = (uint32_t*)(sm + SD_UP);
    float* sDiag = sm + SD_DIAG;
    float* sPart = sm + SD_PART;
    unsigned short* sKp16 = (unsigned short*)(sm + SD_KP16);
    uint32_t*       sKp32 = (uint32_t*)(sm + SD_KP16);
    unsigned short* sVt16 = (unsigned short*)(sm + SD_VT);
    uint32_t*       sVt32 = (uint32_t*)(sm + SD_VT);

    int tid = threadIdx.x;
    int lane = tid & 31, wid = tid >> 5;
    int g = lane >> 2, t = lane & 3;
    int rt = wid & 3;
    int mh = wid >> 2;
    int r0 = rt*16 + g, r1 = r0 + 8;
    int bidx = blockIdx.x, blk = bidx & 31, bh = bidx >> 5;
    int b = bh / Hq, h = bh % Hq;
    int t0 = blk * 64;
    (void)blk;

    const float* ksrc = key   + ((size_t)(b*Tq + t0)*Hq + h)*Eq;
    const float* qsrc = query + ((size_t)(b*Tq + t0)*Hq + h)*Eq;
    uint32_t* gk = g_kbf + (size_t)bidx * 4096;
    uint32_t* gq = g_qbf + (size_t)bidx * 4096;
    for (int i = tid; i < 2048; i += 256) {
        int row = i >> 5, eh = i & 31;
        uint32_t hi, lo;
        float2 vk = *(const float2*)(ksrc + (size_t)row*ROWSTRIDE + eh*2);
        split2_bf16(vk.x, vk.y, hi, lo);
        uTk[row*36 + eh] = hi;
        uTk[2304 + row*36 + eh] = lo;
        gk[row*32 + eh] = hi;
        gk[2048 + row*32 + eh] = lo;
        float2 vq = *(const float2*)(qsrc + (size_t)row*ROWSTRIDE + eh*2);
        split2_bf16(vq.x, vq.y, hi, lo);
        uTq[row*36 + eh] = hi;
        uTq[2304 + row*36 + eh] = lo;
        gq[row*32 + eh] = hi;
        gq[2048 + row*32 + eh] = lo;
    }
    __syncthreads();
    if (tid < 128) {
        int path = tid >> 6, row = tid & 63;
        const uint32_t* uT = path ? uTq : uTk;
        float s = 0.f;
#pragma unroll
        for (int eh = 0; eh < 32; ++eh) {
            uint32_t hu = uT[row*36 + eh], lu = uT[2304 + row*36 + eh];
            float x0 = bf16lo_f(hu) + bf16lo_f(lu);
            float x1 = bf16hi_f(hu) + bf16hi_f(lu);
            s += x0*x0 + x1*x1;
        }
        sDiag[tid] = 0.0625f * s;
    }
    __syncthreads();
    float dg0 = sDiag[r0], dg1 = sDiag[r1];

    uint32_t* kpb = g_kpb + (size_t)bidx * 8192;
    uint32_t* qpb = g_qpb + (size_t)bidx * 8192;

#pragma unroll 1
    for (int c = 0; c < 4; ++c) {
        __syncthreads();
        {
            const uint4* pb = (const uint4*)(g_pbf + c*4096);
            for (int i = tid; i < 1024; i += 256) {
                uint4 v4 = pb[i];
                int pl = (i >> 9);
                int i2 = i & 511;
                int mm = i2 >> 3, e4 = (i2 & 7)*4;
                *(uint4*)(uP + pl*2304 + mm*36 + e4) = v4;
            }
        }
        __syncthreads();

        float Ck[4][4], Cq[4][4];
#pragma unroll
        for (int mt = 0; mt < 4; ++mt)
#pragma unroll
            for (int k = 0; k < 4; ++k) { Ck[mt][k] = 0.f; Cq[mt][k] = 0.f; }

#pragma unroll
        for (int kc = 0; kc < 4; ++kc) {
            int k8 = kc*8;
            uint32_t kh0 = uTk[r0*36 + k8 + t],     kh1 = uTk[r1*36 + k8 + t];
            uint32_t kh2 = uTk[r0*36 + k8 + t + 4], kh3 = uTk[r1*36 + k8 + t + 4];
            uint32_t kl0 = uTk[2304 + r0*36 + k8 + t],     kl1 = uTk[2304 + r1*36 + k8 + t];
            uint32_t kl2 = uTk[2304 + r0*36 + k8 + t + 4], kl3 = uTk[2304 + r1*36 + k8 + t + 4];
            uint32_t qh0 = uTq[r0*36 + k8 + t],     qh1 = uTq[r1*36 + k8 + t];
            uint32_t qh2 = uTq[r0*36 + k8 + t + 4], qh3 = uTq[r1*36 + k8 + t + 4];
            uint32_t ql0 = uTq[2304 + r0*36 + k8 + t],     ql1 = uTq[2304 + r1*36 + k8 + t];
            uint32_t ql2 = uTq[2304 + r0*36 + k8 + t + 4], ql3 = uTq[2304 + r1*36 + k8 + t + 4];
#pragma unroll
            for (int mt = 0; mt < 4; ++mt) {
                int mc = mh*32 + mt*8 + g;
                uint32_t bh0 = uP[mc*36 + k8 + t],        bh1 = uP[mc*36 + k8 + t + 4];
                uint32_t bl0 = uP[2304 + mc*36 + k8 + t], bl1 = uP[2304 + mc*36 + k8 + t + 4];
                mma_bf16(Ck[mt], kh0,kh1,kh2,kh3, bh0,bh1);
                mma_bf16(Ck[mt], kh0,kh1,kh2,kh3, bl0,bl1);
                mma_bf16(Ck[mt], kl0,kl1,kl2,kl3, bh0,bh1);
                mma_bf16(Cq[mt], qh0,qh1,qh2,qh3, bh0,bh1);
                mma_bf16(Cq[mt], qh0,qh1,qh2,qh3, bl0,bl1);
                mma_bf16(Cq[mt], ql0,ql1,ql2,ql3, bh0,bh1);
            }
        }

#pragma unroll
        for (int mt = 0; mt < 4; ++mt) {
            int m0 = c*64 + mh*32 + mt*8 + 2*t;
            int mp = m0 >> 1;
            float e0 = __expf(Ck[mt][0] - dg0);
            float e1 = __expf(Ck[mt][1] - dg0);
            float e2 = __expf(Ck[mt][2] - dg1);
            float e3 = __expf(Ck[mt][3] - dg1);
            uint32_t p0 = pack_f16(e0*KS, e1*KS);
            uint32_t p1 = pack_f16(e2*KS, e3*KS);
            kpb[r0*128 + mp] = p0;
            kpb[r1*128 + mp] = p1;
            sKp16[m0*72 + r0]     = (unsigned short)(p0 & 0xffffu);
            sKp16[(m0+1)*72 + r0] = (unsigned short)(p0 >> 16);
            sKp16[m0*72 + r1]     = (unsigned short)(p1 & 0xffffu);
            sKp16[(m0+1)*72 + r1] = (unsigned short)(p1 >> 16);
            float pm0 = f16lo(p0) + f16lo(p1);
            float pm1 = f16hi(p0) + f16hi(p1);
            pm0 += __shfl_xor_sync(0xffffffffu, pm0, 4);
            pm0 += __shfl_xor_sync(0xffffffffu, pm0, 8);
            pm0 += __shfl_xor_sync(0xffffffffu, pm0, 16);
            pm1 += __shfl_xor_sync(0xffffffffu, pm1, 4);
            pm1 += __shfl_xor_sync(0xffffffffu, pm1, 8);
            pm1 += __shfl_xor_sync(0xffffffffu, pm1, 16);
            if (g == 0) {
                sPart[rt*256 + m0]     = pm0;
                sPart[rt*256 + m0 + 1] = pm1;
            }
            qpb[r0*128 + mp] = pack_f16(__expf(Cq[mt][0] - SQ), __expf(Cq[mt][1] - SQ));
            qpb[r1*128 + mp] = pack_f16(__expf(Cq[mt][2] - SQ), __expf(Cq[mt][3] - SQ));
        }
    }

    {
        const float* vb = value + ((size_t)(b*Tq + t0)*Hq + h)*Eq;
        for (int i2 = tid; i2 < 1024; i2 += 256) {
            int j = i2 >> 4, d0 = (i2 & 15)*4;
            float4 v4 = *(const float4*)(vb + (size_t)j*ROWSTRIDE + d0);
            sVt16[(d0+0)*72 + j] = __half_as_ushort(__float2half_rn(v4.x));
            sVt16[(d0+1)*72 + j] = __half_as_ushort(__float2half_rn(v4.y));
            sVt16[(d0+2)*72 + j] = __half_as_ushort(__float2half_rn(v4.z));
            sVt16[(d0+3)*72 + j] = __half_as_ushort(__float2half_rn(v4.w));
        }
    }
    __syncthreads();

    g_kpspart[(size_t)bidx*256 + tid] =
        sPart[tid] + sPart[256+tid] + sPart[512+tid] + sPart[768+tid];
    if (tid < 64)
        g_qls[bh*Tq + t0 + tid] = SQ - sDiag[64 + tid] - HALF_LOG_M;

    float KC[2][8][4];
#pragma unroll
    for (int it = 0; it < 2; ++it)
#pragma unroll
        for (int nt = 0; nt < 8; ++nt)
#pragma unroll
            for (int k = 0; k < 4; ++k) KC[it][nt][k] = 0.f;

#pragma unroll
    for (int kc = 0; kc < 4; ++kc) {
        int k8 = kc*8;
        uint32_t a[2][4];
#pragma unroll
        for (int it = 0; it < 2; ++it) {
            int rb = wid*32 + it*16;
            a[it][0] = sKp32[(rb+g)*36 + k8 + t];
            a[it][1] = sKp32[(rb+g+8)*36 + k8 + t];
            a[it][2] = sKp32[(rb+g)*36 + k8 + t + 4];
            a[it][3] = sKp32[(rb+g+8)*36 + k8 + t + 4];
        }
#pragma unroll
        for (int nt = 0; nt < 8; ++nt) {
            int d = nt*8 + g;
            uint32_t b0 = sVt32[d*36 + k8 + t], b1 = sVt32[d*36 + k8 + t + 4];
#pragma unroll
            for (int it = 0; it < 2; ++it)
                mma_f16(KC[it][nt], a[it][0],a[it][1],a[it][2],a[it][3], b0,b1);
        }
    }
    float* kvp = g_kvpart + (size_t)bidx * 16384;
#pragma unroll
    for (int it = 0; it < 2; ++it) {
        int m0 = wid*32 + it*16 + g;
#pragma unroll
        for (int nt = 0; nt < 8; ++nt) {
            int d = nt*8 + 2*t;
            *(float2*)(kvp + (size_t)m0*64 + d)     = make_float2(KC[it][nt][0], KC[it][nt][1]);
            *(float2*)(kvp + (size_t)(m0+8)*64 + d) = make_float2(KC[it][nt][2], KC[it][nt][3]);
        }
    }
}

// ---------------- kernel 2: reduce partials -> totals (f32) ----------------
__global__ void reduce_kernel() {
    int idx = blockIdx.x*256 + threadIdx.x;
    if (idx < BH*Mq*Eq) {
        int bh = idx >> 14;
        int rem = idx & 16383;
        float s = 0.f;
#pragma unroll
        for (int p = 0; p < 32; ++p) s += g_kvpart[(size_t)(bh*32 + p)*16384 + rem];
        g_kvtot[idx] = s;
    }
    if (idx < BH*Mq) {
        int bh = idx >> 8; int m = idx & 255;
        float s = 0.f;
#pragma unroll
        for (int p = 0; p < 32; ++p) s += g_kpspart[(bh*32 + p)*256 + m];
        g_kps[idx] = s;
    }
}

// ---------------- kernel 2c: per-q-block complements ----------------
__global__ __launch_bounds__(256) void compl_kernel() {
    int bidx = blockIdx.x, blk = bidx & 31, bh = bidx >> 5;
    int m = threadIdx.x;
    // kps complement
    float kc = g_kps[bh*Mq + m];
    const float* parts[3];
    int nv = 0;
#pragma unroll
    for (int w = -1; w <= 1; ++w) {
        int nb = blk + w;
        if (nb >= 0 && nb < NB) {
            kc -= g_kpspart[(size_t)(bh*32 + nb)*256 + m];
            parts[nv++] = g_kvpart + (size_t)(bh*32 + nb)*16384 + m*64;
        }
    }
    g_kpscmp[(size_t)bidx*256 + m] = kc;
    // kv complement rows: [d][m] fp16
    const float* tot = g_kvtot + (size_t)bh*16384 + m*64;
    unsigned short* outp = g_kvcmp + (size_t)bidx*16384;
#pragma unroll 4
    for (int d = 0; d < 64; ++d) {
        float s = tot[d];
        for (int v = 0; v < nv; ++v) s -= parts[v][d];
        outp[d*256 + m] = __half_as_ushort(__float2half_rn(s));
    }
}

// ---------------- kernel 4: main — dp-free data path ----------------
#define O_QT   0
#define O_KT   4608
#define O_QPP  9216
#define O_WORK 17664   // u32 8448: [0,2304)=E16, [2304,4608)=Vt; later full = KVp
#define O_KPS  26112
#define O_QLS  26368
#define O_SSE  26432
#define O_QPK  26688
#define O_LN   27200
#define O_PS   27264
#define SM_MAIN_FLOATS 27328

__global__ __launch_bounds__(512,2) void main_kernel(const float* __restrict__ value,
                                                     float* __restrict__ out) {
    extern __shared__ float smm[];
    uint32_t* uQT  = (uint32_t*)(smm + O_QT);
    uint32_t* uKT  = (uint32_t*)(smm + O_KT);
    uint32_t* sQPp = (uint32_t*)(smm + O_QPP);
    uint32_t* uWork = (uint32_t*)(smm + O_WORK);
    uint32_t* sE16 = uWork;
    uint32_t* sVt  = uWork + 2304;
    unsigned short* sVt16 = (unsigned short*)sVt;
    uint32_t* sKVp = uWork;
    float* sKps = smm + O_KPS;
    float* sQls = smm + O_QLS;
    float* sSe  = smm + O_SSE;
    float* sQpk = smm + O_QPK;
    float* sLn  = smm + O_LN;
    float* sPs  = smm + O_PS;

    int tid = threadIdx.x;
    int lane = tid & 31, wid = tid >> 5;
    int g = lane >> 2, t = lane & 3;
    int iw = wid & 3, jh = wid >> 2;
    int i0 = iw * 16;
    int bidx = blockIdx.x, blk = bidx & 31, bh = bidx >> 5;
    int b = bh / Hq, h = bh % Hq;
    int t0 = blk * 64;
    int r0 = i0 + g, r1 = r0 + 8;

    // ---- phase 0 ----
    {
        const uint32_t* gq = g_qbf + (size_t)bidx*4096;
        for (int i = tid; i < 2048; i += 512) {
            int row = i >> 5, eh = i & 31;
            uQT[row*36 + eh]        = gq[i];
            uQT[2304 + row*36 + eh] = gq[2048 + i];
        }
        const uint4* qp4 = (const uint4*)(g_qpb + (size_t)bidx*8192);
        for (int i = tid; i < 2048; i += 512) {
            int row = i >> 5, mp0 = (i & 31)*4;
            *(uint4*)(sQPp + row*132 + mp0) = qp4[i];
        }
        if (tid < 256) sKps[tid] = g_kpscmp[(size_t)bidx*256 + tid];
        if (tid < 64)  sQls[tid] = g_qls[bh*Tq + t0 + tid];
    }

    float accE[2][4];
#pragma unroll
    for (int dt = 0; dt < 2; ++dt)
#pragma unroll
        for (int c = 0; c < 4; ++c) accE[dt][c] = 0.f;
    float seR0 = 0.f, seR1 = 0.f;

    // ---- neighbor loop ----
#pragma unroll 1
    for (int nw = 0; nw < 3; ++nw) {
        int nb = blk - 1 + nw;
        if (nb < 0 || nb >= NB) continue;
        size_t kb = (size_t)(bh*32 + nb);
        __syncthreads();   // S0: prior QK/EV readers done
        {
            const uint32_t* gk = g_kbf + kb*4096;
            for (int i = tid; i < 2048; i += 512) {
                int row = i >> 5, eh = i & 31;
                uKT[row*36 + eh]        = gk[i];
                uKT[2304 + row*36 + eh] = gk[2048 + i];
            }
        }
        __syncthreads();   // S1

        float Cqk[2][4];
#pragma unroll
        for (int jt = 0; jt < 2; ++jt)
#pragma unroll
            for (int c = 0; c < 4; ++c) Cqk[jt][c] = 0.f;

        // QK: bf16 3-term split
#pragma unroll
        for (int kc = 0; kc < 4; ++kc) {
            int k8 = kc*8;
            uint32_t ah0 = uQT[r0*36 + k8 + t],     ah1 = uQT[r1*36 + k8 + t];
            uint32_t ah2 = uQT[r0*36 + k8 + t + 4], ah3 = uQT[r1*36 + k8 + t + 4];
            uint32_t al0 = uQT[2304 + r0*36 + k8 + t],     al1 = uQT[2304 + r1*36 + k8 + t];
            uint32_t al2 = uQT[2304 + r0*36 + k8 + t + 4], al3 = uQT[2304 + r1*36 + k8 + t + 4];
#pragma unroll
            for (int jt = 0; jt < 2; ++jt) {
                int j = jh*16 + jt*8 + g;
                uint32_t bh0 = uKT[j*36 + k8 + t],        bh1 = uKT[j*36 + k8 + t + 4];
                uint32_t bl0 = uKT[2304 + j*36 + k8 + t], bl1 = uKT[2304 + j*36 + k8 + t + 4];
                mma_bf16(Cqk[jt], ah0,ah1,ah2,ah3, bh0,bh1);
                mma_bf16(Cqk[jt], ah0,ah1,ah2,ah3, bl0,bl1);
                mma_bf16(Cqk[jt], al0,al1,al2,al3, bh0,bh1);
            }
        }

        // E pack (fp16) + row sums; stage V transposed fp16
#pragma unroll
        for (int jt = 0; jt < 2; ++jt) {
            int j0 = jh*16 + jt*8;
            float e00 = __expf(TEMP*Cqk[jt][0]);
            float e01 = __expf(TEMP*Cqk[jt][1]);
            float e10 = __expf(TEMP*Cqk[jt][2]);
            float e11 = __expf(TEMP*Cqk[jt][3]);
            seR0 += e00 + e01;  seR1 += e10 + e11;
            int jp = (j0 >> 1) + t;
            sE16[r0*36 + jp] = pack_f16(e00, e01);
            sE16[r1*36 + jp] = pack_f16(e10, e11);
        }
        {
            const float* vb = value + ((size_t)(b*Tq + nb*64)*Hq + h)*Eq;
            for (int i2 = tid; i2 < 1024; i2 += 512) {
                int j = i2 >> 4, d0 = (i2 & 15)*4;
                float4 v4 = *(const float4*)(vb + (size_t)j*ROWSTRIDE + d0);
                sVt16[(d0+0)*72 + j] = __half_as_ushort(__float2half_rn(v4.x));
                sVt16[(d0+1)*72 + j] = __half_as_ushort(__float2half_rn(v4.y));
                sVt16[(d0+2)*72 + j] = __half_as_ushort(__float2half_rn(v4.z));
                sVt16[(d0+3)*72 + j] = __half_as_ushort(__float2half_rn(v4.w));
            }
        }
        __syncthreads();   // S2

        // accE += E.V
#pragma unroll
        for (int kc = 0; kc < 4; ++kc) {
            int k8 = kc*8;
            uint32_t aE0 = sE16[r0*36 + k8 + t],     aE1 = sE16[r1*36 + k8 + t];
            uint32_t aE2 = sE16[r0*36 + k8 + t + 4], aE3 = sE16[r1*36 + k8 + t + 4];
#pragma unroll
            for (int dt = 0; dt < 2; ++dt) {
                int d = jh*16 + dt*8 + g;
                uint32_t b0 = sVt[d*36 + k8 + t], b1 = sVt[d*36 + k8 + t + 4];
                mma_f16(accE[dt], aE0,aE1,aE2,aE3, b0,b1);
            }
        }
    }

    // ---- row sums ----
    seR0 += __shfl_xor_sync(0xffffffffu, seR0, 1);
    seR0 += __shfl_xor_sync(0xffffffffu, seR0, 2);
    seR1 += __shfl_xor_sync(0xffffffffu, seR1, 1);
    seR1 += __shfl_xor_sync(0xffffffffu, seR1, 2);
    __syncthreads();   // EV reads done before overwriting work region
    if (t == 0) { sSe[jh*64 + r0] = seR0; sSe[jh*64 + r1] = seR1; }
    // stage kv complement fp16 [d][132]
    {
        const uint4* kv4 = (const uint4*)(g_kvcmp + (size_t)bidx*16384);
        for (int i = tid; i < 2048; i += 512) {
            int row = i >> 5, mp0 = (i & 31)*4;
            *(uint4*)(sKVp + row*132 + mp0) = kv4[i];
        }
    }
    // qp_kp_1 complement partials
    {
        int part = tid >> 6, ii = tid & 63;
        float s = 0.f;
#pragma unroll
        for (int k = 0; k < 16; ++k) {
            uint32_t u = sQPp[ii*132 + part*16 + k];
            int m2 = (part*16 + k)*2;
            s += f16lo(u) * sKps[m2] + f16hi(u) * sKps[m2+1];
        }
        sQpk[part*64 + ii] = s;
    }
    __syncthreads();

    // C2 = q'. kv_cmp (fp16, scaled)
    float C2[2][4];
#pragma unroll
    for (int dt = 0; dt < 2; ++dt)
#pragma unroll
        for (int c = 0; c < 4; ++c) C2[dt][c] = 0.f;
#pragma unroll
    for (int kc = 0; kc < 16; ++kc) {
        int k8 = kc*8;
        uint32_t a0 = sQPp[r0*132 + k8 + t],     a1 = sQPp[r1*132 + k8 + t];
        uint32_t a2 = sQPp[r0*132 + k8 + t + 4], a3 = sQPp[r1*132 + k8 + t + 4];
#pragma unroll
        for (int dt = 0; dt < 2; ++dt) {
            int d = jh*16 + dt*8 + g;
            uint32_t b0 = sKVp[d*132 + k8 + t], b1 = sKVp[d*132 + k8 + t + 4];
            mma_f16(C2[dt], a0,a1,a2,a3, b0,b1);
        }
    }

    if (tid < 64) {
        float qpk1 = 0.f;
#pragma unroll
        for (int p = 0; p < 8; ++p) qpk1 += sQpk[p*64 + tid];
        float se = sSe[tid] + sSe[64+tid] + sSe[128+tid] + sSe[192+tid];
        float lse = __logf(se);
        float pls = sQls[tid] - HALF_LOG_M;
        float lr  = __logf(fmaxf(qpk1, 1e-30f)) + LOG_KS + pls;
        float mxv = fmaxf(lse, lr);
        float ln  = mxv + log1pf(__expf(-fabsf(lse - lr)));
        sLn[tid] = ln;
        sPs[tid] = __expf(pls - ln);
    }
    __syncthreads();
    float iE0 = __expf(-sLn[r0]), iE1 = __expf(-sLn[r1]);
    float ps0 = sPs[r0] * 256.f, ps1 = sPs[r1] * 256.f;

    // ---- epilogue: out = accE*exp(-ln) + C2cmp*ps ----
    float* ob = out + ((size_t)(b*Tq + t0)*Hq + h)*Eq;
#pragma unroll
    for (int dt = 0; dt < 2; ++dt) {
        int d = jh*16 + dt*8 + 2*t;
        float2 o0, o1;
        o0.x = accE[dt][0]*iE0 + C2[dt][0]*ps0;
        o0.y = accE[dt][1]*iE0 + C2[dt][1]*ps0;
        o1.x = accE[dt][2]*iE1 + C2[dt][2]*ps1;
        o1.y = accE[dt][3]*iE1 + C2[dt][3]*ps1;
        *(float2*)(ob + (size_t)r0*ROWSTRIDE + d) = o0;
        *(float2*)(ob + (size_t)r1*ROWSTRIDE + d) = o1;
    }
}

// ---------------- launch ----------------
extern "C" void kernel_launch(void* const* d_in, const int* in_sizes, int n_in,
                              void* d_out, int out_size) {
    const float* query = (const float*)d_in[0];
    const float* key   = (const float*)d_in[1];
    const float* value = (const float*)d_in[2];
    const float* proj  = (const float*)d_in[3];
    float* out = (float*)d_out;

    const int SM_SIDES = SM_SIDES_FLOATS * 4;  // 105984
    const int SM_MAIN  = SM_MAIN_FLOATS * 4;   // 109312

    cudaFuncSetAttribute(sides_kernel, cudaFuncAttributeMaxDynamicSharedMemorySize, SM_SIDES);
    cudaFuncSetAttribute(main_kernel,  cudaFuncAttributeMaxDynamicSharedMemorySize, SM_MAIN);

    pinit_kernel<<<32, 256>>>(proj);
    sides_kernel<<<BH*NB, 256, SM_SIDES>>>(key, query, value);
    reduce_kernel<<<(BH*Mq*Eq + 255)/256, 256>>>();
    compl_kernel<<<BH*NB, 256>>>();
    main_kernel<<<BH*NB, 512, SM_MAIN>>>(value, out);
}

// round 15
// speedup vs baseline: 2.0337x; 2.0337x over previous
#include <cuda_runtime.h>
#include <cuda_bf16.h>
#include <cuda_fp16.h>
#include <math.h>
#include <stdint.h>

#define Bq 2
#define Tq 2048
#define Hq 12
#define Eq 64
#define Mq 256
#define NB 32
#define BH 24
#define ROWSTRIDE (Hq*Eq)

#define TEMP 0.125f
#define DN 0.35355339059327379f
#define HALF_LOG_M 2.7725887222397811f
#define NEG_INF __int_as_float(0xff800000)
#define KS 0.00390625f                 // 2^-8 prime-side (k) scale
#define LOG_KS 5.5451774444795624753f  // -log(KS) = 8*ln2
#define SQ 8.0f                        // fixed q-side shift

// ---------------- device scratch ----------------
__device__ uint32_t g_pbf[16384];                // proj*DN bf16 planes
__device__ uint32_t g_qbf[BH*NB*4096];           // raw q bf16 planes [row][e]
__device__ uint32_t g_kbf[BH*NB*4096];           // raw k bf16 planes
__device__ __align__(16) uint32_t g_qpb[BH*NB*8192]; // q'=exp(qd-SQ) fp16 packed [i][m/2]
__device__ __align__(16) uint32_t g_kpb[BH*NB*8192]; // k'*KS fp16 packed [j][m/2]
__device__ float g_qls [BH*Tq];
__device__ float g_kps [BH*Mq];                  // KS-scaled totals
__device__ float g_kvtot [BH*Mq*Eq];             // KS-scaled kv totals [m][d] f32
__device__ float g_kvpart [BH*32*Mq*Eq];         // KS-scaled kv partials [m][d]
__device__ float g_kpspart[BH*32*Mq];

// ---------------- helpers ----------------
__device__ __forceinline__ void mma_bf16(float c[4],
        uint32_t a0, uint32_t a1, uint32_t a2, uint32_t a3, uint32_t b0, uint32_t b1)
{
    asm volatile(
        "mma.sync.aligned.m16n8k16.row.col.f32.bf16.bf16.f32 "
        "{%0,%1,%2,%3}, {%4,%5,%6,%7}, {%8,%9}, {%0,%1,%2,%3};\n"
        : "+f"(c[0]), "+f"(c[1]), "+f"(c[2]), "+f"(c[3])
        : "r"(a0), "r"(a1), "r"(a2), "r"(a3), "r"(b0), "r"(b1));
}

__device__ __forceinline__ void mma_f16(float c[4],
        uint32_t a0, uint32_t a1, uint32_t a2, uint32_t a3, uint32_t b0, uint32_t b1)
{
    asm volatile(
        "mma.sync.aligned.m16n8k16.row.col.f32.f16.f16.f32 "
        "{%0,%1,%2,%3}, {%4,%5,%6,%7}, {%8,%9}, {%0,%1,%2,%3};\n"
        : "+f"(c[0]), "+f"(c[1]), "+f"(c[2]), "+f"(c[3])
        : "r"(a0), "r"(a1), "r"(a2), "r"(a3), "r"(b0), "r"(b1));
}

__device__ __forceinline__ void split2_bf16(float x, float y, uint32_t &hi, uint32_t &lo) {
    __nv_bfloat16 hx = __float2bfloat16(x);
    __nv_bfloat16 hy = __float2bfloat16(y);
    __nv_bfloat16 lx = __float2bfloat16(x - __bfloat162float(hx));
    __nv_bfloat16 ly = __float2bfloat16(y - __bfloat162float(hy));
    hi = ((uint32_t)__bfloat16_as_ushort(hy) << 16) | (uint32_t)__bfloat16_as_ushort(hx);
    lo = ((uint32_t)__bfloat16_as_ushort(ly) << 16) | (uint32_t)__bfloat16_as_ushort(lx);
}

__device__ __forceinline__ uint32_t pack_f16(float x, float y) {
    __half2 h = __floats2half2_rn(x, y);
    return *reinterpret_cast<uint32_t*>(&h);
}
__device__ __forceinline__ float f16lo(uint32_t u) {
    return __half2float(__ushort_as_half((unsigned short)(u & 0xffffu)));
}
__device__ __forceinline__ float f16hi(uint32_t u) {
    return __half2float(__ushort_as_half((unsigned short)(u >> 16)));
}
__device__ __forceinline__ float bf16lo_f(uint32_t u) {
    return __bfloat162float(__ushort_as_bfloat16((unsigned short)(u & 0xffffu)));
}
__device__ __forceinline__ float bf16hi_f(uint32_t u) {
    return __bfloat162float(__ushort_as_bfloat16((unsigned short)(u >> 16)));
}

// ---------------- kernel 0: proj planes precompute ----------------
__global__ void pinit_kernel(const float* __restrict__ proj) {
    int idx = blockIdx.x*256 + threadIdx.x;
    if (idx < 8192) {
        int c = idx >> 11, rem = idx & 2047;
        int mm = rem >> 5, eh = rem & 31;
        float2 v = *(const float2*)(proj + (size_t)(c*64 + mm)*64 + eh*2);
        uint32_t hi, lo;
        split2_bf16(v.x * DN, v.y * DN, hi, lo);
        g_pbf[c*4096 + mm*32 + eh]        = hi;
        g_pbf[c*4096 + 2048 + mm*32 + eh] = lo;
    }
}

// ---------------- kernel 1: sides (unchanged from R13) ----------------
#define SD_UTQ  4608
#define SD_UP   9216
#define SD_DIAG 13824
#define SD_PART 13952
#define SD_KP16 14976
#define SD_VT   24192
#define SM_SIDES_FLOATS 26496

__global__ __launch_bounds__(256,2) void sides_kernel(const float* __restrict__ key,
                                                      const float* __restrict__ query,
                                                      const float* __restrict__ value) {
    extern __shared__ float sm[];
    uint32_t* uTk = (uint32_t*)sm;
    uint32_t* uTq = (uint32_t*)(sm + SD_UTQ);
    uint32_t* uP  = (uint32_t*)(sm + SD_UP);
    float* sDiag = sm + SD_DIAG;
    float* sPart = sm + SD_PART;
    unsigned short* sKp16 = (unsigned short*)(sm + SD_KP16);
    uint32_t*       sKp32 = (uint32_t*)(sm + SD_KP16);
    unsigned short* sVt16 = (unsigned short*)(sm + SD_VT);
    uint32_t*       sVt32 = (uint32_t*)(sm + SD_VT);

    int tid = threadIdx.x;
    int lane = tid & 31, wid = tid >> 5;
    int g = lane >> 2, t = lane & 3;
    int rt = wid & 3;
    int mh = wid >> 2;
    int r0 = rt*16 + g, r1 = r0 + 8;
    int bidx = blockIdx.x, blk = bidx & 31, bh = bidx >> 5;
    int b = bh / Hq, h = bh % Hq;
    int t0 = blk * 64;
    (void)blk;

    const float* ksrc = key   + ((size_t)(b*Tq + t0)*Hq + h)*Eq;
    const float* qsrc = query + ((size_t)(b*Tq + t0)*Hq + h)*Eq;
    uint32_t* gk = g_kbf + (size_t)bidx * 4096;
    uint32_t* gq = g_qbf + (size_t)bidx * 4096;
    for (int i = tid; i < 2048; i += 256) {
        int row = i >> 5, eh = i & 31;
        uint32_t hi, lo;
        float2 vk = *(const float2*)(ksrc + (size_t)row*ROWSTRIDE + eh*2);
        split2_bf16(vk.x, vk.y, hi, lo);
        uTk[row*36 + eh] = hi;
        uTk[2304 + row*36 + eh] = lo;
        gk[row*32 + eh] = hi;
        gk[2048 + row*32 + eh] = lo;
        float2 vq = *(const float2*)(qsrc + (size_t)row*ROWSTRIDE + eh*2);
        split2_bf16(vq.x, vq.y, hi, lo);
        uTq[row*36 + eh] = hi;
        uTq[2304 + row*36 + eh] = lo;
        gq[row*32 + eh] = hi;
        gq[2048 + row*32 + eh] = lo;
    }
    __syncthreads();
    if (tid < 128) {
        int path = tid >> 6, row = tid & 63;
        const uint32_t* uT = path ? uTq : uTk;
        float s = 0.f;
#pragma unroll
        for (int eh = 0; eh < 32; ++eh) {
            uint32_t hu = uT[row*36 + eh], lu = uT[2304 + row*36 + eh];
            float x0 = bf16lo_f(hu) + bf16lo_f(lu);
            float x1 = bf16hi_f(hu) + bf16hi_f(lu);
            s += x0*x0 + x1*x1;
        }
        sDiag[tid] = 0.0625f * s;
    }
    __syncthreads();
    float dg0 = sDiag[r0], dg1 = sDiag[r1];

    uint32_t* kpb = g_kpb + (size_t)bidx * 8192;
    uint32_t* qpb = g_qpb + (size_t)bidx * 8192;

#pragma unroll 1
    for (int c = 0; c < 4; ++c) {
        __syncthreads();
        {
            const uint4* pb = (const uint4*)(g_pbf + c*4096);
            for (int i = tid; i < 1024; i += 256) {
                uint4 v4 = pb[i];
                int pl = (i >> 9);
                int i2 = i & 511;
                int mm = i2 >> 3, e4 = (i2 & 7)*4;
                *(uint4*)(uP + pl*2304 + mm*36 + e4) = v4;
            }
        }
        __syncthreads();

        float Ck[4][4], Cq[4][4];
#pragma unroll
        for (int mt = 0; mt < 4; ++mt)
#pragma unroll
            for (int k = 0; k < 4; ++k) { Ck[mt][k] = 0.f; Cq[mt][k] = 0.f; }

#pragma unroll
        for (int kc = 0; kc < 4; ++kc) {
            int k8 = kc*8;
            uint32_t kh0 = uTk[r0*36 + k8 + t],     kh1 = uTk[r1*36 + k8 + t];
            uint32_t kh2 = uTk[r0*36 + k8 + t + 4], kh3 = uTk[r1*36 + k8 + t + 4];
            uint32_t kl0 = uTk[2304 + r0*36 + k8 + t],     kl1 = uTk[2304 + r1*36 + k8 + t];
            uint32_t kl2 = uTk[2304 + r0*36 + k8 + t + 4], kl3 = uTk[2304 + r1*36 + k8 + t + 4];
            uint32_t qh0 = uTq[r0*36 + k8 + t],     qh1 = uTq[r1*36 + k8 + t];
            uint32_t qh2 = uTq[r0*36 + k8 + t + 4], qh3 = uTq[r1*36 + k8 + t + 4];
            uint32_t ql0 = uTq[2304 + r0*36 + k8 + t],     ql1 = uTq[2304 + r1*36 + k8 + t];
            uint32_t ql2 = uTq[2304 + r0*36 + k8 + t + 4], ql3 = uTq[2304 + r1*36 + k8 + t + 4];
#pragma unroll
            for (int mt = 0; mt < 4; ++mt) {
                int mc = mh*32 + mt*8 + g;
                uint32_t bh0 = uP[mc*36 + k8 + t],        bh1 = uP[mc*36 + k8 + t + 4];
                uint32_t bl0 = uP[2304 + mc*36 + k8 + t], bl1 = uP[2304 + mc*36 + k8 + t + 4];
                mma_bf16(Ck[mt], kh0,kh1,kh2,kh3, bh0,bh1);
                mma_bf16(Ck[mt], kh0,kh1,kh2,kh3, bl0,bl1);
                mma_bf16(Ck[mt], kl0,kl1,kl2,kl3, bh0,bh1);
                mma_bf16(Cq[mt], qh0,qh1,qh2,qh3, bh0,bh1);
                mma_bf16(Cq[mt], qh0,qh1,qh2,qh3, bl0,bl1);
                mma_bf16(Cq[mt], ql0,ql1,ql2,ql3, bh0,bh1);
            }
        }

#pragma unroll
        for (int mt = 0; mt < 4; ++mt) {
            int m0 = c*64 + mh*32 + mt*8 + 2*t;
            int mp = m0 >> 1;
            float e0 = __expf(Ck[mt][0] - dg0);
            float e1 = __expf(Ck[mt][1] - dg0);
            float e2 = __expf(Ck[mt][2] - dg1);
            float e3 = __expf(Ck[mt][3] - dg1);
            uint32_t p0 = pack_f16(e0*KS, e1*KS);
            uint32_t p1 = pack_f16(e2*KS, e3*KS);
            kpb[r0*128 + mp] = p0;
            kpb[r1*128 + mp] = p1;
            sKp16[m0*72 + r0]     = (unsigned short)(p0 & 0xffffu);
            sKp16[(m0+1)*72 + r0] = (unsigned short)(p0 >> 16);
            sKp16[m0*72 + r1]     = (unsigned short)(p1 & 0xffffu);
            sKp16[(m0+1)*72 + r1] = (unsigned short)(p1 >> 16);
            float pm0 = f16lo(p0) + f16lo(p1);
            float pm1 = f16hi(p0) + f16hi(p1);
            pm0 += __shfl_xor_sync(0xffffffffu, pm0, 4);
            pm0 += __shfl_xor_sync(0xffffffffu, pm0, 8);
            pm0 += __shfl_xor_sync(0xffffffffu, pm0, 16);
            pm1 += __shfl_xor_sync(0xffffffffu, pm1, 4);
            pm1 += __shfl_xor_sync(0xffffffffu, pm1, 8);
            pm1 += __shfl_xor_sync(0xffffffffu, pm1, 16);
            if (g == 0) {
                sPart[rt*256 + m0]     = pm0;
                sPart[rt*256 + m0 + 1] = pm1;
            }
            qpb[r0*128 + mp] = pack_f16(__expf(Cq[mt][0] - SQ), __expf(Cq[mt][1] - SQ));
            qpb[r1*128 + mp] = pack_f16(__expf(Cq[mt][2] - SQ), __expf(Cq[mt][3] - SQ));
        }
    }

    {
        const float* vb = value + ((size_t)(b*Tq + t0)*Hq + h)*Eq;
        for (int i2 = tid; i2 < 1024; i2 += 256) {
            int j = i2 >> 4, d0 = (i2 & 15)*4;
            float4 v4 = *(const float4*)(vb + (size_t)j*ROWSTRIDE + d0);
            sVt16[(d0+0)*72 + j] = __half_as_ushort(__float2half_rn(v4.x));
            sVt16[(d0+1)*72 + j] = __half_as_ushort(__float2half_rn(v4.y));
            sVt16[(d0+2)*72 + j] = __half_as_ushort(__float2half_rn(v4.z));
            sVt16[(d0+3)*72 + j] = __half_as_ushort(__float2half_rn(v4.w));
        }
    }
    __syncthreads();

    g_kpspart[(size_t)bidx*256 + tid] =
        sPart[tid] + sPart[256+tid] + sPart[512+tid] + sPart[768+tid];
    if (tid < 64)
        g_qls[bh*Tq + t0 + tid] = SQ - sDiag[64 + tid] - HALF_LOG_M;

    float KC[2][8][4];
#pragma unroll
    for (int it = 0; it < 2; ++it)
#pragma unroll
        for (int nt = 0; nt < 8; ++nt)
#pragma unroll
            for (int k = 0; k < 4; ++k) KC[it][nt][k] = 0.f;

#pragma unroll
    for (int kc = 0; kc < 4; ++kc) {
        int k8 = kc*8;
        uint32_t a[2][4];
#pragma unroll
        for (int it = 0; it < 2; ++it) {
            int rb = wid*32 + it*16;
            a[it][0] = sKp32[(rb+g)*36 + k8 + t];
            a[it][1] = sKp32[(rb+g+8)*36 + k8 + t];
            a[it][2] = sKp32[(rb+g)*36 + k8 + t + 4];
            a[it][3] = sKp32[(rb+g+8)*36 + k8 + t + 4];
        }
#pragma unroll
        for (int nt = 0; nt < 8; ++nt) {
            int d = nt*8 + g;
            uint32_t b0 = sVt32[d*36 + k8 + t], b1 = sVt32[d*36 + k8 + t + 4];
#pragma unroll
            for (int it = 0; it < 2; ++it)
                mma_f16(KC[it][nt], a[it][0],a[it][1],a[it][2],a[it][3], b0,b1);
        }
    }
    float* kvp = g_kvpart + (size_t)bidx * 16384;
#pragma unroll
    for (int it = 0; it < 2; ++it) {
        int m0 = wid*32 + it*16 + g;
#pragma unroll
        for (int nt = 0; nt < 8; ++nt) {
            int d = nt*8 + 2*t;
            *(float2*)(kvp + (size_t)m0*64 + d)     = make_float2(KC[it][nt][0], KC[it][nt][1]);
            *(float2*)(kvp + (size_t)(m0+8)*64 + d) = make_float2(KC[it][nt][2], KC[it][nt][3]);
        }
    }
}

// ---------------- kernel 2: reduce partials -> totals (f32) ----------------
__global__ void reduce_kernel() {
    int idx = blockIdx.x*256 + threadIdx.x;
    if (idx < BH*Mq*Eq) {
        int bh = idx >> 14;
        int rem = idx & 16383;
        float s = 0.f;
#pragma unroll
        for (int p = 0; p < 32; ++p) s += g_kvpart[(size_t)(bh*32 + p)*16384 + rem];
        g_kvtot[idx] = s;
    }
    if (idx < BH*Mq) {
        int bh = idx >> 8; int m = idx & 255;
        float s = 0.f;
#pragma unroll
        for (int p = 0; p < 32; ++p) s += g_kpspart[(bh*32 + p)*256 + m];
        g_kps[idx] = s;
    }
}

// ---------------- kernel 4: main — dp-free, inline complements ----------------
#define O_QT   0
#define O_KT   4608
#define O_QPP  9216
#define O_WORK 17664   // u32 8448: [0,2304)=E16, [2304,4608)=Vt; later full = KVp
#define O_KPS  26112
#define O_QLS  26368
#define O_SSE  26432
#define O_QPK  26688
#define O_LN   27200
#define O_PS   27264
#define SM_MAIN_FLOATS 27328

__global__ __launch_bounds__(512,2) void main_kernel(const float* __restrict__ value,
                                                     float* __restrict__ out) {
    extern __shared__ float smm[];
    uint32_t* uQT  = (uint32_t*)(smm + O_QT);
    uint32_t* uKT  = (uint32_t*)(smm + O_KT);
    uint32_t* sQPp = (uint32_t*)(smm + O_QPP);
    uint32_t* uWork = (uint32_t*)(smm + O_WORK);
    uint32_t* sE16 = uWork;
    uint32_t* sVt  = uWork + 2304;
    unsigned short* sVt16 = (unsigned short*)sVt;
    uint32_t* sKVp = uWork;
    float* sKps = smm + O_KPS;
    float* sQls = smm + O_QLS;
    float* sSe  = smm + O_SSE;
    float* sQpk = smm + O_QPK;
    float* sLn  = smm + O_LN;
    float* sPs  = smm + O_PS;

    int tid = threadIdx.x;
    int lane = tid & 31, wid = tid >> 5;
    int g = lane >> 2, t = lane & 3;
    int iw = wid & 3, jh = wid >> 2;
    int i0 = iw * 16;
    int bidx = blockIdx.x, blk = bidx & 31, bh = bidx >> 5;
    int b = bh / Hq, h = bh % Hq;
    int t0 = blk * 64;
    int r0 = i0 + g, r1 = r0 + 8;

    // ---- phase 0 ----
    {
        const uint32_t* gq = g_qbf + (size_t)bidx*4096;
        for (int i = tid; i < 2048; i += 512) {
            int row = i >> 5, eh = i & 31;
            uQT[row*36 + eh]        = gq[i];
            uQT[2304 + row*36 + eh] = gq[2048 + i];
        }
        const uint4* qp4 = (const uint4*)(g_qpb + (size_t)bidx*8192);
        for (int i = tid; i < 2048; i += 512) {
            int row = i >> 5, mp0 = (i & 31)*4;
            *(uint4*)(sQPp + row*132 + mp0) = qp4[i];
        }
        if (tid < 256) {
            float kc = g_kps[bh*Mq + tid];
#pragma unroll
            for (int w = -1; w <= 1; ++w) {
                int nb = blk + w;
                if (nb >= 0 && nb < NB)
                    kc -= g_kpspart[(size_t)(bh*32 + nb)*256 + tid];
            }
            sKps[tid] = kc;
        }
        if (tid < 64)  sQls[tid] = g_qls[bh*Tq + t0 + tid];
    }

    float accE[2][4];
#pragma unroll
    for (int dt = 0; dt < 2; ++dt)
#pragma unroll
        for (int c = 0; c < 4; ++c) accE[dt][c] = 0.f;
    float seR0 = 0.f, seR1 = 0.f;

    // ---- neighbor loop ----
#pragma unroll 1
    for (int nw = 0; nw < 3; ++nw) {
        int nb = blk - 1 + nw;
        if (nb < 0 || nb >= NB) continue;
        size_t kb = (size_t)(bh*32 + nb);
        __syncthreads();   // S0
        {
            const uint32_t* gk = g_kbf + kb*4096;
            for (int i = tid; i < 2048; i += 512) {
                int row = i >> 5, eh = i & 31;
                uKT[row*36 + eh]        = gk[i];
                uKT[2304 + row*36 + eh] = gk[2048 + i];
            }
        }
        __syncthreads();   // S1

        float Cqk[2][4];
#pragma unroll
        for (int jt = 0; jt < 2; ++jt)
#pragma unroll
            for (int c = 0; c < 4; ++c) Cqk[jt][c] = 0.f;

        // QK: bf16 3-term split
#pragma unroll
        for (int kc = 0; kc < 4; ++kc) {
            int k8 = kc*8;
            uint32_t ah0 = uQT[r0*36 + k8 + t],     ah1 = uQT[r1*36 + k8 + t];
            uint32_t ah2 = uQT[r0*36 + k8 + t + 4], ah3 = uQT[r1*36 + k8 + t + 4];
            uint32_t al0 = uQT[2304 + r0*36 + k8 + t],     al1 = uQT[2304 + r1*36 + k8 + t];
            uint32_t al2 = uQT[2304 + r0*36 + k8 + t + 4], al3 = uQT[2304 + r1*36 + k8 + t + 4];
#pragma unroll
            for (int jt = 0; jt < 2; ++jt) {
                int j = jh*16 + jt*8 + g;
                uint32_t bh0 = uKT[j*36 + k8 + t],        bh1 = uKT[j*36 + k8 + t + 4];
                uint32_t bl0 = uKT[2304 + j*36 + k8 + t], bl1 = uKT[2304 + j*36 + k8 + t + 4];
                mma_bf16(Cqk[jt], ah0,ah1,ah2,ah3, bh0,bh1);
                mma_bf16(Cqk[jt], ah0,ah1,ah2,ah3, bl0,bl1);
                mma_bf16(Cqk[jt], al0,al1,al2,al3, bh0,bh1);
            }
        }

        // E pack (fp16) + row sums; stage V transposed fp16
#pragma unroll
        for (int jt = 0; jt < 2; ++jt) {
            int j0 = jh*16 + jt*8;
            float e00 = __expf(TEMP*Cqk[jt][0]);
            float e01 = __expf(TEMP*Cqk[jt][1]);
            float e10 = __expf(TEMP*Cqk[jt][2]);
            float e11 = __expf(TEMP*Cqk[jt][3]);
            seR0 += e00 + e01;  seR1 += e10 + e11;
            int jp = (j0 >> 1) + t;
            sE16[r0*36 + jp] = pack_f16(e00, e01);
            sE16[r1*36 + jp] = pack_f16(e10, e11);
        }
        {
            const float* vb = value + ((size_t)(b*Tq + nb*64)*Hq + h)*Eq;
            for (int i2 = tid; i2 < 1024; i2 += 512) {
                int j = i2 >> 4, d0 = (i2 & 15)*4;
                float4 v4 = *(const float4*)(vb + (size_t)j*ROWSTRIDE + d0);
                sVt16[(d0+0)*72 + j] = __half_as_ushort(__float2half_rn(v4.x));
                sVt16[(d0+1)*72 + j] = __half_as_ushort(__float2half_rn(v4.y));
                sVt16[(d0+2)*72 + j] = __half_as_ushort(__float2half_rn(v4.z));
                sVt16[(d0+3)*72 + j] = __half_as_ushort(__float2half_rn(v4.w));
            }
        }
        __syncthreads();   // S2

        // accE += E.V
#pragma unroll
        for (int kc = 0; kc < 4; ++kc) {
            int k8 = kc*8;
            uint32_t aE0 = sE16[r0*36 + k8 + t],     aE1 = sE16[r1*36 + k8 + t];
            uint32_t aE2 = sE16[r0*36 + k8 + t + 4], aE3 = sE16[r1*36 + k8 + t + 4];
#pragma unroll
            for (int dt = 0; dt < 2; ++dt) {
                int d = jh*16 + dt*8 + g;
                uint32_t b0 = sVt[d*36 + k8 + t], b1 = sVt[d*36 + k8 + t + 4];
                mma_f16(accE[dt], aE0,aE1,aE2,aE3, b0,b1);
            }
        }
    }

    // ---- row sums ----
    seR0 += __shfl_xor_sync(0xffffffffu, seR0, 1);
    seR0 += __shfl_xor_sync(0xffffffffu, seR0, 2);
    seR1 += __shfl_xor_sync(0xffffffffu, seR1, 1);
    seR1 += __shfl_xor_sync(0xffffffffu, seR1, 2);
    __syncthreads();   // EV reads done before overwriting work region
    if (t == 0) { sSe[jh*64 + r0] = seR0; sSe[jh*64 + r1] = seR1; }

    // ---- stage kv complement: f32 [m][d] -> packed fp16 [d][132] ----
    {
        const float4* tot4 = (const float4*)(g_kvtot + (size_t)bh*16384);
        const float4* ptrs[3];
        int nv = 0;
#pragma unroll
        for (int w = -1; w <= 1; ++w) {
            int nb = blk + w;
            if (nb >= 0 && nb < NB)
                ptrs[nv++] = (const float4*)(g_kvpart + (size_t)(bh*32 + nb)*16384);
        }
        for (int i = tid; i < 2048; i += 512) {
            int mp = i >> 4, d4q = i & 15;
            int idx0 = (2*mp)*16 + d4q;
            int idx1 = idx0 + 16;
            float4 a = tot4[idx0], bq = tot4[idx1];
            for (int v = 0; v < nv; ++v) {
                float4 pa = ptrs[v][idx0], pb = ptrs[v][idx1];
                a.x -= pa.x; a.y -= pa.y; a.z -= pa.z; a.w -= pa.w;
                bq.x -= pb.x; bq.y -= pb.y; bq.z -= pb.z; bq.w -= pb.w;
            }
            int d0 = d4q*4;
            sKVp[(d0+0)*132 + mp] = pack_f16(a.x, bq.x);
            sKVp[(d0+1)*132 + mp] = pack_f16(a.y, bq.y);
            sKVp[(d0+2)*132 + mp] = pack_f16(a.z, bq.z);
            sKVp[(d0+3)*132 + mp] = pack_f16(a.w, bq.w);
        }
    }
    // qp_kp_1 complement partials
    {
        int part = tid >> 6, ii = tid & 63;
        float s = 0.f;
#pragma unroll
        for (int k = 0; k < 16; ++k) {
            uint32_t u = sQPp[ii*132 + part*16 + k];
            int m2 = (part*16 + k)*2;
            s += f16lo(u) * sKps[m2] + f16hi(u) * sKps[m2+1];
        }
        sQpk[part*64 + ii] = s;
    }
    __syncthreads();

    // C2 = q'. kv_cmp (fp16, scaled)
    float C2[2][4];
#pragma unroll
    for (int dt = 0; dt < 2; ++dt)
#pragma unroll
        for (int c = 0; c < 4; ++c) C2[dt][c] = 0.f;
#pragma unroll
    for (int kc = 0; kc < 16; ++kc) {
        int k8 = kc*8;
        uint32_t a0 = sQPp[r0*132 + k8 + t],     a1 = sQPp[r1*132 + k8 + t];
        uint32_t a2 = sQPp[r0*132 + k8 + t + 4], a3 = sQPp[r1*132 + k8 + t + 4];
#pragma unroll
        for (int dt = 0; dt < 2; ++dt) {
            int d = jh*16 + dt*8 + g;
            uint32_t b0 = sKVp[d*132 + k8 + t], b1 = sKVp[d*132 + k8 + t + 4];
            mma_f16(C2[dt], a0,a1,a2,a3, b0,b1);
        }
    }

    if (tid < 64) {
        float qpk1 = 0.f;
#pragma unroll
        for (int p = 0; p < 8; ++p) qpk1 += sQpk[p*64 + tid];
        float se = sSe[tid] + sSe[64+tid] + sSe[128+tid] + sSe[192+tid];
        float lse = __logf(se);
        float pls = sQls[tid] - HALF_LOG_M;
        float lr  = __logf(fmaxf(qpk1, 1e-30f)) + LOG_KS + pls;
        float mxv = fmaxf(lse, lr);
        float ln  = mxv + log1pf(__expf(-fabsf(lse - lr)));
        sLn[tid] = ln;
        sPs[tid] = __expf(pls - ln);
    }
    __syncthreads();
    float iE0 = __expf(-sLn[r0]), iE1 = __expf(-sLn[r1]);
    float ps0 = sPs[r0] * 256.f, ps1 = sPs[r1] * 256.f;

    // ---- epilogue: out = accE*exp(-ln) + C2cmp*ps ----
    float* ob = out + ((size_t)(b*Tq + t0)*Hq + h)*Eq;
#pragma unroll
    for (int dt = 0; dt < 2; ++dt) {
        int d = jh*16 + dt*8 + 2*t;
        float2 o0, o1;
        o0.x = accE[dt][0]*iE0 + C2[dt][0]*ps0;
        o0.y = accE[dt][1]*iE0 + C2[dt][1]*ps0;
        o1.x = accE[dt][2]*iE1 + C2[dt][2]*ps1;
        o1.y = accE[dt][3]*iE1 + C2[dt][3]*ps1;
        *(float2*)(ob + (size_t)r0*ROWSTRIDE + d) = o0;
        *(float2*)(ob + (size_t)r1*ROWSTRIDE + d) = o1;
    }
}

// ---------------- launch ----------------
extern "C" void kernel_launch(void* const* d_in, const int* in_sizes, int n_in,
                              void* d_out, int out_size) {
    const float* query = (const float*)d_in[0];
    const float* key   = (const float*)d_in[1];
    const float* value = (const float*)d_in[2];
    const float* proj  = (const float*)d_in[3];
    float* out = (float*)d_out;

    const int SM_SIDES = SM_SIDES_FLOATS * 4;  // 105984
    const int SM_MAIN  = SM_MAIN_FLOATS * 4;   // 109312

    cudaFuncSetAttribute(sides_kernel, cudaFuncAttributeMaxDynamicSharedMemorySize, SM_SIDES);
    cudaFuncSetAttribute(main_kernel,  cudaFuncAttributeMaxDynamicSharedMemorySize, SM_MAIN);

    pinit_kernel<<<32, 256>>>(proj);
    sides_kernel<<<BH*NB, 256, SM_SIDES>>>(key, query, value);
    reduce_kernel<<<(BH*Mq*Eq + 255)/256, 256>>>();
    main_kernel<<<BH*NB, 512, SM_MAIN>>>(value, out);
}

// round 16
// speedup vs baseline: 2.0911x; 1.0282x over previous
#include <cuda_runtime.h>
#include <cuda_bf16.h>
#include <cuda_fp16.h>
#include <math.h>
#include <stdint.h>

#define Bq 2
#define Tq 2048
#define Hq 12
#define Eq 64
#define Mq 256
#define NB 32
#define BH 24
#define ROWSTRIDE (Hq*Eq)

#define TEMP 0.125f
#define DN 0.35355339059327379f
#define HALF_LOG_M 2.7725887222397811f
#define NEG_INF __int_as_float(0xff800000)
#define KS 0.00390625f                 // 2^-8 prime-side (k) scale
#define LOG_KS 5.5451774444795624753f  // -log(KS) = 8*ln2
#define SQ 8.0f                        // fixed q-side shift

// ---------------- device scratch ----------------
__device__ uint32_t g_pbf[16384];                // proj*DN bf16 planes
__device__ uint32_t g_qbf[BH*NB*4096];           // raw q bf16 planes [row][e]
__device__ uint32_t g_kbf[BH*NB*4096];           // raw k bf16 planes
__device__ __align__(16) uint32_t g_qpb[BH*NB*8192]; // q'=exp(qd-SQ) fp16 packed [i][m/2]
__device__ __align__(16) uint32_t g_kpb[BH*NB*8192]; // k'*KS fp16 packed [j][m/2]
__device__ float g_qls [BH*Tq];
__device__ float g_kps [BH*Mq];                  // KS-scaled totals
__device__ float g_kvtot [BH*Mq*Eq];             // KS-scaled kv totals [m][d] f32
__device__ float g_kvpart [BH*32*Mq*Eq];         // KS-scaled kv partials [m][d]
__device__ float g_kpspart[BH*32*Mq];

// ---------------- helpers ----------------
__device__ __forceinline__ void mma_bf16(float c[4],
        uint32_t a0, uint32_t a1, uint32_t a2, uint32_t a3, uint32_t b0, uint32_t b1)
{
    asm volatile(
        "mma.sync.aligned.m16n8k16.row.col.f32.bf16.bf16.f32 "
        "{%0,%1,%2,%3}, {%4,%5,%6,%7}, {%8,%9}, {%0,%1,%2,%3};\n"
        : "+f"(c[0]), "+f"(c[1]), "+f"(c[2]), "+f"(c[3])
        : "r"(a0), "r"(a1), "r"(a2), "r"(a3), "r"(b0), "r"(b1));
}

__device__ __forceinline__ void mma_f16(float c[4],
        uint32_t a0, uint32_t a1, uint32_t a2, uint32_t a3, uint32_t b0, uint32_t b1)
{
    asm volatile(
        "mma.sync.aligned.m16n8k16.row.col.f32.f16.f16.f32 "
        "{%0,%1,%2,%3}, {%4,%5,%6,%7}, {%8,%9}, {%0,%1,%2,%3};\n"
        : "+f"(c[0]), "+f"(c[1]), "+f"(c[2]), "+f"(c[3])
        : "r"(a0), "r"(a1), "r"(a2), "r"(a3), "r"(b0), "r"(b1));
}

__device__ __forceinline__ void split2_bf16(float x, float y, uint32_t &hi, uint32_t &lo) {
    __nv_bfloat16 hx = __float2bfloat16(x);
    __nv_bfloat16 hy = __float2bfloat16(y);
    __nv_bfloat16 lx = __float2bfloat16(x - __bfloat162float(hx));
    __nv_bfloat16 ly = __float2bfloat16(y - __bfloat162float(hy));
    hi = ((uint32_t)__bfloat16_as_ushort(hy) << 16) | (uint32_t)__bfloat16_as_ushort(hx);
    lo = ((uint32_t)__bfloat16_as_ushort(ly) << 16) | (uint32_t)__bfloat16_as_ushort(lx);
}

__device__ __forceinline__ uint32_t pack_f16(float x, float y) {
    __half2 h = __floats2half2_rn(x, y);
    return *reinterpret_cast<uint32_t*>(&h);
}
__device__ __forceinline__ float f16lo(uint32_t u) {
    return __half2float(__ushort_as_half((unsigned short)(u & 0xffffu)));
}
__device__ __forceinline__ float f16hi(uint32_t u) {
    return __half2float(__ushort_as_half((unsigned short)(u >> 16)));
}
__device__ __forceinline__ float bf16lo_f(uint32_t u) {
    return __bfloat162float(__ushort_as_bfloat16((unsigned short)(u & 0xffffu)));
}
__device__ __forceinline__ float bf16hi_f(uint32_t u) {
    return __bfloat162float(__ushort_as_bfloat16((unsigned short)(u >> 16)));
}

// ---------------- kernel 0: proj planes precompute ----------------
__global__ void pinit_kernel(const float* __restrict__ proj) {
    int idx = blockIdx.x*256 + threadIdx.x;
    if (idx < 8192) {
        int c = idx >> 11, rem = idx & 2047;
        int mm = rem >> 5, eh = rem & 31;
        float2 v = *(const float2*)(proj + (size_t)(c*64 + mm)*64 + eh*2);
        uint32_t hi, lo;
        split2_bf16(v.x * DN, v.y * DN, hi, lo);
        g_pbf[c*4096 + mm*32 + eh]        = hi;
        g_pbf[c*4096 + 2048 + mm*32 + eh] = lo;
    }
}

// ---------------- kernel 1: sides — 512 threads, 16 warps ----------------
#define SD_UTQ  4608
#define SD_UP   9216
#define SD_DIAG 13824
#define SD_PART 13952
#define SD_KP16 14976
#define SD_VT   24192
#define SM_SIDES_FLOATS 26496

__global__ __launch_bounds__(512,2) void sides_kernel(const float* __restrict__ key,
                                                      const float* __restrict__ query,
                                                      const float* __restrict__ value) {
    extern __shared__ float sm[];
    uint32_t* uTk = (uint32_t*)sm;
    uint32_t* uTq = (uint32_t*)(sm + SD_UTQ);
    uint32_t* uP  = (uint32_t*)(sm + SD_UP);
    float* sDiag = sm + SD_DIAG;
    float* sPart = sm + SD_PART;
    unsigned short* sKp16 = (unsigned short*)(sm + SD_KP16);
    uint32_t*       sKp32 = (uint32_t*)(sm + SD_KP16);
    unsigned short* sVt16 = (unsigned short*)(sm + SD_VT);
    uint32_t*       sVt32 = (uint32_t*)(sm + SD_VT);

    int tid = threadIdx.x;
    int lane = tid & 31, wid = tid >> 5;
    int g = lane >> 2, t = lane & 3;
    int rt = wid & 3;          // row tile of 16
    int mh = wid >> 2;         // feature quarter (0..3) within 64-chunk -> 16 cols
    int r0 = rt*16 + g, r1 = r0 + 8;
    int bidx = blockIdx.x, blk = bidx & 31, bh = bidx >> 5;
    int b = bh / Hq, h = bh % Hq;
    int t0 = blk * 64;
    (void)blk;

    const float* ksrc = key   + ((size_t)(b*Tq + t0)*Hq + h)*Eq;
    const float* qsrc = query + ((size_t)(b*Tq + t0)*Hq + h)*Eq;
    uint32_t* gk = g_kbf + (size_t)bidx * 4096;
    uint32_t* gq = g_qbf + (size_t)bidx * 4096;
    for (int i = tid; i < 2048; i += 512) {
        int row = i >> 5, eh = i & 31;
        uint32_t hi, lo;
        float2 vk = *(const float2*)(ksrc + (size_t)row*ROWSTRIDE + eh*2);
        split2_bf16(vk.x, vk.y, hi, lo);
        uTk[row*36 + eh] = hi;
        uTk[2304 + row*36 + eh] = lo;
        gk[row*32 + eh] = hi;
        gk[2048 + row*32 + eh] = lo;
        float2 vq = *(const float2*)(qsrc + (size_t)row*ROWSTRIDE + eh*2);
        split2_bf16(vq.x, vq.y, hi, lo);
        uTq[row*36 + eh] = hi;
        uTq[2304 + row*36 + eh] = lo;
        gq[row*32 + eh] = hi;
        gq[2048 + row*32 + eh] = lo;
    }
    __syncthreads();
    if (tid < 128) {
        int path = tid >> 6, row = tid & 63;
        const uint32_t* uT = path ? uTq : uTk;
        float s = 0.f;
#pragma unroll
        for (int eh = 0; eh < 32; ++eh) {
            uint32_t hu = uT[row*36 + eh], lu = uT[2304 + row*36 + eh];
            float x0 = bf16lo_f(hu) + bf16lo_f(lu);
            float x1 = bf16hi_f(hu) + bf16hi_f(lu);
            s += x0*x0 + x1*x1;
        }
        sDiag[tid] = 0.0625f * s;
    }
    __syncthreads();
    float dg0 = sDiag[r0], dg1 = sDiag[r1];

    uint32_t* kpb = g_kpb + (size_t)bidx * 8192;
    uint32_t* qpb = g_qpb + (size_t)bidx * 8192;

#pragma unroll 1
    for (int c = 0; c < 4; ++c) {
        __syncthreads();
        {
            const uint4* pb = (const uint4*)(g_pbf + c*4096);
            for (int i = tid; i < 1024; i += 512) {
                uint4 v4 = pb[i];
                int pl = (i >> 9);
                int i2 = i & 511;
                int mm = i2 >> 3, e4 = (i2 & 7)*4;
                *(uint4*)(uP + pl*2304 + mm*36 + e4) = v4;
            }
        }
        __syncthreads();

        float Ck[2][4], Cq[2][4];
#pragma unroll
        for (int mt = 0; mt < 2; ++mt)
#pragma unroll
            for (int k = 0; k < 4; ++k) { Ck[mt][k] = 0.f; Cq[mt][k] = 0.f; }

#pragma unroll
        for (int kc = 0; kc < 4; ++kc) {
            int k8 = kc*8;
            uint32_t kh0 = uTk[r0*36 + k8 + t],     kh1 = uTk[r1*36 + k8 + t];
            uint32_t kh2 = uTk[r0*36 + k8 + t + 4], kh3 = uTk[r1*36 + k8 + t + 4];
            uint32_t kl0 = uTk[2304 + r0*36 + k8 + t],     kl1 = uTk[2304 + r1*36 + k8 + t];
            uint32_t kl2 = uTk[2304 + r0*36 + k8 + t + 4], kl3 = uTk[2304 + r1*36 + k8 + t + 4];
            uint32_t qh0 = uTq[r0*36 + k8 + t],     qh1 = uTq[r1*36 + k8 + t];
            uint32_t qh2 = uTq[r0*36 + k8 + t + 4], qh3 = uTq[r1*36 + k8 + t + 4];
            uint32_t ql0 = uTq[2304 + r0*36 + k8 + t],     ql1 = uTq[2304 + r1*36 + k8 + t];
            uint32_t ql2 = uTq[2304 + r0*36 + k8 + t + 4], ql3 = uTq[2304 + r1*36 + k8 + t + 4];
#pragma unroll
            for (int mt = 0; mt < 2; ++mt) {
                int mc = mh*16 + mt*8 + g;
                uint32_t bh0 = uP[mc*36 + k8 + t],        bh1 = uP[mc*36 + k8 + t + 4];
                uint32_t bl0 = uP[2304 + mc*36 + k8 + t], bl1 = uP[2304 + mc*36 + k8 + t + 4];
                mma_bf16(Ck[mt], kh0,kh1,kh2,kh3, bh0,bh1);
                mma_bf16(Ck[mt], kh0,kh1,kh2,kh3, bl0,bl1);
                mma_bf16(Ck[mt], kl0,kl1,kl2,kl3, bh0,bh1);
                mma_bf16(Cq[mt], qh0,qh1,qh2,qh3, bh0,bh1);
                mma_bf16(Cq[mt], qh0,qh1,qh2,qh3, bl0,bl1);
                mma_bf16(Cq[mt], ql0,ql1,ql2,ql3, bh0,bh1);
            }
        }

#pragma unroll
        for (int mt = 0; mt < 2; ++mt) {
            int m0 = c*64 + mh*16 + mt*8 + 2*t;
            int mp = m0 >> 1;
            float e0 = __expf(Ck[mt][0] - dg0);
            float e1 = __expf(Ck[mt][1] - dg0);
            float e2 = __expf(Ck[mt][2] - dg1);
            float e3 = __expf(Ck[mt][3] - dg1);
            uint32_t p0 = pack_f16(e0*KS, e1*KS);
            uint32_t p1 = pack_f16(e2*KS, e3*KS);
            kpb[r0*128 + mp] = p0;
            kpb[r1*128 + mp] = p1;
            sKp16[m0*72 + r0]     = (unsigned short)(p0 & 0xffffu);
            sKp16[(m0+1)*72 + r0] = (unsigned short)(p0 >> 16);
            sKp16[m0*72 + r1]     = (unsigned short)(p1 & 0xffffu);
            sKp16[(m0+1)*72 + r1] = (unsigned short)(p1 >> 16);
            float pm0 = f16lo(p0) + f16lo(p1);
            float pm1 = f16hi(p0) + f16hi(p1);
            pm0 += __shfl_xor_sync(0xffffffffu, pm0, 4);
            pm0 += __shfl_xor_sync(0xffffffffu, pm0, 8);
            pm0 += __shfl_xor_sync(0xffffffffu, pm0, 16);
            pm1 += __shfl_xor_sync(0xffffffffu, pm1, 4);
            pm1 += __shfl_xor_sync(0xffffffffu, pm1, 8);
            pm1 += __shfl_xor_sync(0xffffffffu, pm1, 16);
            if (g == 0) {
                sPart[rt*256 + m0]     = pm0;
                sPart[rt*256 + m0 + 1] = pm1;
            }
            qpb[r0*128 + mp] = pack_f16(__expf(Cq[mt][0] - SQ), __expf(Cq[mt][1] - SQ));
            qpb[r1*128 + mp] = pack_f16(__expf(Cq[mt][2] - SQ), __expf(Cq[mt][3] - SQ));
        }
    }

    {
        const float* vb = value + ((size_t)(b*Tq + t0)*Hq + h)*Eq;
        for (int i2 = tid; i2 < 1024; i2 += 512) {
            int j = i2 >> 4, d0 = (i2 & 15)*4;
            float4 v4 = *(const float4*)(vb + (size_t)j*ROWSTRIDE + d0);
            sVt16[(d0+0)*72 + j] = __half_as_ushort(__float2half_rn(v4.x));
            sVt16[(d0+1)*72 + j] = __half_as_ushort(__float2half_rn(v4.y));
            sVt16[(d0+2)*72 + j] = __half_as_ushort(__float2half_rn(v4.z));
            sVt16[(d0+3)*72 + j] = __half_as_ushort(__float2half_rn(v4.w));
        }
    }
    __syncthreads();

    if (tid < 256)
        g_kpspart[(size_t)bidx*256 + tid] =
            sPart[tid] + sPart[256+tid] + sPart[512+tid] + sPart[768+tid];
    if (tid < 64)
        g_qls[bh*Tq + t0 + tid] = SQ - sDiag[64 + tid] - HALF_LOG_M;

    // kv partials: 16 warps x 16 m-rows
    float KC[8][4];
#pragma unroll
    for (int nt = 0; nt < 8; ++nt)
#pragma unroll
        for (int k = 0; k < 4; ++k) KC[nt][k] = 0.f;

#pragma unroll
    for (int kc = 0; kc < 4; ++kc) {
        int k8 = kc*8;
        int rb = wid*16;
        uint32_t a0 = sKp32[(rb+g)*36 + k8 + t];
        uint32_t a1 = sKp32[(rb+g+8)*36 + k8 + t];
        uint32_t a2 = sKp32[(rb+g)*36 + k8 + t + 4];
        uint32_t a3 = sKp32[(rb+g+8)*36 + k8 + t + 4];
#pragma unroll
        for (int nt = 0; nt < 8; ++nt) {
            int d = nt*8 + g;
            uint32_t b0 = sVt32[d*36 + k8 + t], b1 = sVt32[d*36 + k8 + t + 4];
            mma_f16(KC[nt], a0,a1,a2,a3, b0,b1);
        }
    }
    float* kvp = g_kvpart + (size_t)bidx * 16384;
    {
        int m0 = wid*16 + g;
#pragma unroll
        for (int nt = 0; nt < 8; ++nt) {
            int d = nt*8 + 2*t;
            *(float2*)(kvp + (size_t)m0*64 + d)     = make_float2(KC[nt][0], KC[nt][1]);
            *(float2*)(kvp + (size_t)(m0+8)*64 + d) = make_float2(KC[nt][2], KC[nt][3]);
        }
    }
}

// ---------------- kernel 2: reduce partials -> totals (f32) ----------------
__global__ void reduce_kernel() {
    int idx = blockIdx.x*256 + threadIdx.x;
    if (idx < BH*Mq*Eq) {
        int bh = idx >> 14;
        int rem = idx & 16383;
        float s = 0.f;
#pragma unroll
        for (int p = 0; p < 32; ++p) s += g_kvpart[(size_t)(bh*32 + p)*16384 + rem];
        g_kvtot[idx] = s;
    }
    if (idx < BH*Mq) {
        int bh = idx >> 8; int m = idx & 255;
        float s = 0.f;
#pragma unroll
        for (int p = 0; p < 32; ++p) s += g_kpspart[(bh*32 + p)*256 + m];
        g_kps[idx] = s;
    }
}

// ---------------- kernel 4: main — dp-free, inline complements (unchanged R15) ----------------
#define O_QT   0
#define O_KT   4608
#define O_QPP  9216
#define O_WORK 17664
#define O_KPS  26112
#define O_QLS  26368
#define O_SSE  26432
#define O_QPK  26688
#define O_LN   27200
#define O_PS   27264
#define SM_MAIN_FLOATS 27328

__global__ __launch_bounds__(512,2) void main_kernel(const float* __restrict__ value,
                                                     float* __restrict__ out) {
    extern __shared__ float smm[];
    uint32_t* uQT  = (uint32_t*)(smm + O_QT);
    uint32_t* uKT  = (uint32_t*)(smm + O_KT);
    uint32_t* sQPp = (uint32_t*)(smm + O_QPP);
    uint32_t* uWork = (uint32_t*)(smm + O_WORK);
    uint32_t* sE16 = uWork;
    uint32_t* sVt  = uWork + 2304;
    unsigned short* sVt16 = (unsigned short*)sVt;
    uint32_t* sKVp = uWork;
    float* sKps = smm + O_KPS;
    float* sQls = smm + O_QLS;
    float* sSe  = smm + O_SSE;
    float* sQpk = smm + O_QPK;
    float* sLn  = smm + O_LN;
    float* sPs  = smm + O_PS;

    int tid = threadIdx.x;
    int lane = tid & 31, wid = tid >> 5;
    int g = lane >> 2, t = lane & 3;
    int iw = wid & 3, jh = wid >> 2;
    int i0 = iw * 16;
    int bidx = blockIdx.x, blk = bidx & 31, bh = bidx >> 5;
    int b = bh / Hq, h = bh % Hq;
    int t0 = blk * 64;
    int r0 = i0 + g, r1 = r0 + 8;

    // ---- phase 0 ----
    {
        const uint32_t* gq = g_qbf + (size_t)bidx*4096;
        for (int i = tid; i < 2048; i += 512) {
            int row = i >> 5, eh = i & 31;
            uQT[row*36 + eh]        = gq[i];
            uQT[2304 + row*36 + eh] = gq[2048 + i];
        }
        const uint4* qp4 = (const uint4*)(g_qpb + (size_t)bidx*8192);
        for (int i = tid; i < 2048; i += 512) {
            int row = i >> 5, mp0 = (i & 31)*4;
            *(uint4*)(sQPp + row*132 + mp0) = qp4[i];
        }
        if (tid < 256) {
            float kc = g_kps[bh*Mq + tid];
#pragma unroll
            for (int w = -1; w <= 1; ++w) {
                int nb = blk + w;
                if (nb >= 0 && nb < NB)
                    kc -= g_kpspart[(size_t)(bh*32 + nb)*256 + tid];
            }
            sKps[tid] = kc;
        }
        if (tid < 64)  sQls[tid] = g_qls[bh*Tq + t0 + tid];
    }

    float accE[2][4];
#pragma unroll
    for (int dt = 0; dt < 2; ++dt)
#pragma unroll
        for (int c = 0; c < 4; ++c) accE[dt][c] = 0.f;
    float seR0 = 0.f, seR1 = 0.f;

    // ---- neighbor loop ----
#pragma unroll 1
    for (int nw = 0; nw < 3; ++nw) {
        int nb = blk - 1 + nw;
        if (nb < 0 || nb >= NB) continue;
        size_t kb = (size_t)(bh*32 + nb);
        __syncthreads();   // S0
        {
            const uint32_t* gk = g_kbf + kb*4096;
            for (int i = tid; i < 2048; i += 512) {
                int row = i >> 5, eh = i & 31;
                uKT[row*36 + eh]        = gk[i];
                uKT[2304 + row*36 + eh] = gk[2048 + i];
            }
        }
        __syncthreads();   // S1

        float Cqk[2][4];
#pragma unroll
        for (int jt = 0; jt < 2; ++jt)
#pragma unroll
            for (int c = 0; c < 4; ++c) Cqk[jt][c] = 0.f;

        // QK: bf16 3-term split
#pragma unroll
        for (int kc = 0; kc < 4; ++kc) {
            int k8 = kc*8;
            uint32_t ah0 = uQT[r0*36 + k8 + t],     ah1 = uQT[r1*36 + k8 + t];
            uint32_t ah2 = uQT[r0*36 + k8 + t + 4], ah3 = uQT[r1*36 + k8 + t + 4];
            uint32_t al0 = uQT[2304 + r0*36 + k8 + t],     al1 = uQT[2304 + r1*36 + k8 + t];
            uint32_t al2 = uQT[2304 + r0*36 + k8 + t + 4], al3 = uQT[2304 + r1*36 + k8 + t + 4];
#pragma unroll
            for (int jt = 0; jt < 2; ++jt) {
                int j = jh*16 + jt*8 + g;
                uint32_t bh0 = uKT[j*36 + k8 + t],        bh1 = uKT[j*36 + k8 + t + 4];
                uint32_t bl0 = uKT[2304 + j*36 + k8 + t], bl1 = uKT[2304 + j*36 + k8 + t + 4];
                mma_bf16(Cqk[jt], ah0,ah1,ah2,ah3, bh0,bh1);
                mma_bf16(Cqk[jt], ah0,ah1,ah2,ah3, bl0,bl1);
                mma_bf16(Cqk[jt], al0,al1,al2,al3, bh0,bh1);
            }
        }

        // E pack (fp16) + row sums; stage V transposed fp16
#pragma unroll
        for (int jt = 0; jt < 2; ++jt) {
            int j0 = jh*16 + jt*8;
            float e00 = __expf(TEMP*Cqk[jt][0]);
            float e01 = __expf(TEMP*Cqk[jt][1]);
            float e10 = __expf(TEMP*Cqk[jt][2]);
            float e11 = __expf(TEMP*Cqk[jt][3]);
            seR0 += e00 + e01;  seR1 += e10 + e11;
            int jp = (j0 >> 1) + t;
            sE16[r0*36 + jp] = pack_f16(e00, e01);
            sE16[r1*36 + jp] = pack_f16(e10, e11);
        }
        {
            const float* vb = value + ((size_t)(b*Tq + nb*64)*Hq + h)*Eq;
            for (int i2 = tid; i2 < 1024; i2 += 512) {
                int j = i2 >> 4, d0 = (i2 & 15)*4;
                float4 v4 = *(const float4*)(vb + (size_t)j*ROWSTRIDE + d0);
                sVt16[(d0+0)*72 + j] = __half_as_ushort(__float2half_rn(v4.x));
                sVt16[(d0+1)*72 + j] = __half_as_ushort(__float2half_rn(v4.y));
                sVt16[(d0+2)*72 + j] = __half_as_ushort(__float2half_rn(v4.z));
                sVt16[(d0+3)*72 + j] = __half_as_ushort(__float2half_rn(v4.w));
            }
        }
        __syncthreads();   // S2

        // accE += E.V
#pragma unroll
        for (int kc = 0; kc < 4; ++kc) {
            int k8 = kc*8;
            uint32_t aE0 = sE16[r0*36 + k8 + t],     aE1 = sE16[r1*36 + k8 + t];
            uint32_t aE2 = sE16[r0*36 + k8 + t + 4], aE3 = sE16[r1*36 + k8 + t + 4];
#pragma unroll
            for (int dt = 0; dt < 2; ++dt) {
                int d = jh*16 + dt*8 + g;
                uint32_t b0 = sVt[d*36 + k8 + t], b1 = sVt[d*36 + k8 + t + 4];
                mma_f16(accE[dt], aE0,aE1,aE2,aE3, b0,b1);
            }
        }
    }

    // ---- row sums ----
    seR0 += __shfl_xor_sync(0xffffffffu, seR0, 1);
    seR0 += __shfl_xor_sync(0xffffffffu, seR0, 2);
    seR1 += __shfl_xor_sync(0xffffffffu, seR1, 1);
    seR1 += __shfl_xor_sync(0xffffffffu, seR1, 2);
    __syncthreads();   // EV reads done before overwriting work region
    if (t == 0) { sSe[jh*64 + r0] = seR0; sSe[jh*64 + r1] = seR1; }

    // ---- stage kv complement: f32 [m][d] -> packed fp16 [d][132] ----
    {
        const float4* tot4 = (const float4*)(g_kvtot + (size_t)bh*16384);
        const float4* ptrs[3];
        int nv = 0;
#pragma unroll
        for (int w = -1; w <= 1; ++w) {
            int nb = blk + w;
            if (nb >= 0 && nb < NB)
                ptrs[nv++] = (const float4*)(g_kvpart + (size_t)(bh*32 + nb)*16384);
        }
        for (int i = tid; i < 2048; i += 512) {
            int mp = i >> 4, d4q = i & 15;
            int idx0 = (2*mp)*16 + d4q;
            int idx1 = idx0 + 16;
            float4 a = tot4[idx0], bq = tot4[idx1];
            for (int v = 0; v < nv; ++v) {
                float4 pa = ptrs[v][idx0], pb = ptrs[v][idx1];
                a.x -= pa.x; a.y -= pa.y; a.z -= pa.z; a.w -= pa.w;
                bq.x -= pb.x; bq.y -= pb.y; bq.z -= pb.z; bq.w -= pb.w;
            }
            int d0 = d4q*4;
            sKVp[(d0+0)*132 + mp] = pack_f16(a.x, bq.x);
            sKVp[(d0+1)*132 + mp] = pack_f16(a.y, bq.y);
            sKVp[(d0+2)*132 + mp] = pack_f16(a.z, bq.z);
            sKVp[(d0+3)*132 + mp] = pack_f16(a.w, bq.w);
        }
    }
    // qp_kp_1 complement partials
    {
        int part = tid >> 6, ii = tid & 63;
        float s = 0.f;
#pragma unroll
        for (int k = 0; k < 16; ++k) {
            uint32_t u = sQPp[ii*132 + part*16 + k];
            int m2 = (part*16 + k)*2;
            s += f16lo(u) * sKps[m2] + f16hi(u) * sKps[m2+1];
        }
        sQpk[part*64 + ii] = s;
    }
    __syncthreads();

    // C2 = q'. kv_cmp (fp16, scaled)
    float C2[2][4];
#pragma unroll
    for (int dt = 0; dt < 2; ++dt)
#pragma unroll
        for (int c = 0; c < 4; ++c) C2[dt][c] = 0.f;
#pragma unroll
    for (int kc = 0; kc < 16; ++kc) {
        int k8 = kc*8;
        uint32_t a0 = sQPp[r0*132 + k8 + t],     a1 = sQPp[r1*132 + k8 + t];
        uint32_t a2 = sQPp[r0*132 + k8 + t + 4], a3 = sQPp[r1*132 + k8 + t + 4];
#pragma unroll
        for (int dt = 0; dt < 2; ++dt) {
            int d = jh*16 + dt*8 + g;
            uint32_t b0 = sKVp[d*132 + k8 + t], b1 = sKVp[d*132 + k8 + t + 4];
            mma_f16(C2[dt], a0,a1,a2,a3, b0,b1);
        }
    }

    if (tid < 64) {
        float qpk1 = 0.f;
#pragma unroll
        for (int p = 0; p < 8; ++p) qpk1 += sQpk[p*64 + tid];
        float se = sSe[tid] + sSe[64+tid] + sSe[128+tid] + sSe[192+tid];
        float lse = __logf(se);
        float pls = sQls[tid] - HALF_LOG_M;
        float lr  = __logf(fmaxf(qpk1, 1e-30f)) + LOG_KS + pls;
        float mxv = fmaxf(lse, lr);
        float ln  = mxv + log1pf(__expf(-fabsf(lse - lr)));
        sLn[tid] = ln;
        sPs[tid] = __expf(pls - ln);
    }
    __syncthreads();
    float iE0 = __expf(-sLn[r0]), iE1 = __expf(-sLn[r1]);
    float ps0 = sPs[r0] * 256.f, ps1 = sPs[r1] * 256.f;

    // ---- epilogue ----
    float* ob = out + ((size_t)(b*Tq + t0)*Hq + h)*Eq;
#pragma unroll
    for (int dt = 0; dt < 2; ++dt) {
        int d = jh*16 + dt*8 + 2*t;
        float2 o0, o1;
        o0.x = accE[dt][0]*iE0 + C2[dt][0]*ps0;
        o0.y = accE[dt][1]*iE0 + C2[dt][1]*ps0;
        o1.x = accE[dt][2]*iE1 + C2[dt][2]*ps1;
        o1.y = accE[dt][3]*iE1 + C2[dt][3]*ps1;
        *(float2*)(ob + (size_t)r0*ROWSTRIDE + d) = o0;
        *(float2*)(ob + (size_t)r1*ROWSTRIDE + d) = o1;
    }
}

// ---------------- launch ----------------
extern "C" void kernel_launch(void* const* d_in, const int* in_sizes, int n_in,
                              void* d_out, int out_size) {
    const float* query = (const float*)d_in[0];
    const float* key   = (const float*)d_in[1];
    const float* value = (const float*)d_in[2];
    const float* proj  = (const float*)d_in[3];
    float* out = (float*)d_out;

    const int SM_SIDES = SM_SIDES_FLOATS * 4;  // 105984
    const int SM_MAIN  = SM_MAIN_FLOATS * 4;   // 109312

    cudaFuncSetAttribute(sides_kernel, cudaFuncAttributeMaxDynamicSharedMemorySize, SM_SIDES);
    cudaFuncSetAttribute(main_kernel,  cudaFuncAttributeMaxDynamicSharedMemorySize, SM_MAIN);

    pinit_kernel<<<32, 256>>>(proj);
    sides_kernel<<<BH*NB, 512, SM_SIDES>>>(key, query, value);
    reduce_kernel<<<(BH*Mq*Eq + 255)/256, 256>>>();
    main_kernel<<<BH*NB, 512, SM_MAIN>>>(value, out);
}